// round 3
// baseline (speedup 1.0000x reference)
#include <cuda_runtime.h>
#include <math.h>

#define NN 16384
#define EE 262144
#define MULT 64
#define SQRT3_INV 0.5773502691896258f

// ---------------- device scratch (no runtime allocation allowed) ------------
__device__ __align__(16) float g_h0[NN * 64];    // [n][k]
__device__ __align__(16) float g_h1[NN * 192];   // [n][c][k]   c-major
__device__ __align__(16) float g_a0[NN * 128];   // [n][2*MUL]
__device__ __align__(16) float g_a1[NN * 384];   // [n][c][128]
__device__ __align__(16) float g_d0[NN * 128];   // [n][2*MUL]
__device__ __align__(16) float g_d1[NN * 192];   // [n][c][64]

__device__ __forceinline__ float silu_f(float x) { return x / (1.0f + expf(-x)); }

__device__ __forceinline__ void red4(float* p, float a, float b, float c, float d) {
    asm volatile("red.global.add.v4.f32 [%0], {%1,%2,%3,%4};"
                 :: "l"(p), "f"(a), "f"(b), "f"(c), "f"(d) : "memory");
}

// ---------------- K1: linear_up ---------------------------------------------
// h0 = (x0 @ Wup0)/8 ; h1[n][c][k] = sum_m x1[n][m][c]*Wup1[m][k] / 8
__global__ void k_linear_up(const float* __restrict__ x0, const float* __restrict__ x1,
                            const float* __restrict__ Wup0, const float* __restrict__ Wup1) {
    __shared__ float sW0[4096];
    __shared__ float sW1[4096];
    __shared__ float sX0[16 * 64];
    __shared__ float sX1[16 * 192];
    int t = threadIdx.x;
    for (int i = t; i < 4096; i += 256) { sW0[i] = Wup0[i]; sW1[i] = Wup1[i]; }
    int nb = blockIdx.x * 16;
    for (int i = t; i < 16 * 64;  i += 256) sX0[i] = x0[nb * 64  + i];
    for (int i = t; i < 16 * 192; i += 256) sX1[i] = x1[nb * 192 + i];
    __syncthreads();
    int k = t & 63, q = t >> 6;
    const float inv = 0.125f;
    if (q == 0) {
        for (int n = 0; n < 16; n++) {
            float acc = 0.f;
            #pragma unroll 16
            for (int m = 0; m < 64; m++) acc += sX0[n * 64 + m] * sW0[m * 64 + k];
            g_h0[(nb + n) * 64 + k] = acc * inv;
        }
    } else {
        int c = q - 1;
        for (int n = 0; n < 16; n++) {
            float acc = 0.f;
            #pragma unroll 16
            for (int m = 0; m < 64; m++) acc += sX1[n * 192 + m * 3 + c] * sW1[m * 64 + k];
            g_h1[(nb + n) * 192 + c * 64 + k] = acc * inv;
        }
    }
}

// ---------------- K2: zero the scatter accumulators --------------------------
__global__ void k_zero() {
    float4 z = make_float4(0.f, 0.f, 0.f, 0.f);
    float4* p0 = (float4*)g_a0;
    float4* p1 = (float4*)g_a1;
    int stride = gridDim.x * blockDim.x;
    for (int i = blockIdx.x * blockDim.x + threadIdx.x; i < NN * 32; i += stride) p0[i] = z;
    for (int i = blockIdx.x * blockDim.x + threadIdx.x; i < NN * 96; i += stride) p1[i] = z;
}

// ---------------- K3: fused radial MLP + tensor product + scatter -----------
// dynamic smem layout (floats):
//   sRw2 [0,16384)  sW [16384,20480)  sRw1 [20480,20992)  sHid [20992,22016)
//   sRE  [22016,22144) sY [22144,22208) ints: sSnd/sRcv at 22208
#define K3_SMEM_BYTES ((22208 + 32) * 4)

__global__ void k_edge(const float* __restrict__ re, const float* __restrict__ y0v,
                       const float* __restrict__ y1v, const int* __restrict__ snd,
                       const int* __restrict__ rcv,
                       const float* __restrict__ Rw1, const float* __restrict__ Rw2) {
    extern __shared__ float sm[];
    float* sRw2 = sm;
    float* sW   = sm + 16384;
    float* sRw1 = sm + 20480;
    float* sHid = sm + 20992;
    float* sRE  = sm + 22016;
    float* sY   = sm + 22144;
    int*   sSnd = (int*)(sm + 22208);
    int*   sRcv = sSnd + 16;

    int t = threadIdx.x;
    for (int i = t; i < 16384; i += 256) sRw2[i] = Rw2[i];
    for (int i = t; i < 512;   i += 256) sRw1[i] = Rw1[i];

    int nchunk = EE / 16;
    for (int ch = blockIdx.x; ch < nchunk; ch += gridDim.x) {
        int e0 = ch * 16;
        if (t < 128) sRE[t] = re[e0 * 8 + t];
        if (t < 16) { sSnd[t] = snd[e0 + t]; sRcv[t] = rcv[e0 + t]; sY[t * 4 + 3] = y0v[e0 + t]; }
        if (t >= 128 && t < 176) { int i = t - 128; sY[(i / 3) * 4 + (i % 3)] = y1v[e0 * 3 + i]; }
        __syncthreads();

        // hidden layer: 16 edges x 64, silu((re@Rw1)/sqrt(8))
        #pragma unroll
        for (int j = 0; j < 4; j++) {
            int idx = t + j * 256;
            int e = idx >> 6, h = idx & 63;
            float acc = 0.f;
            #pragma unroll
            for (int r = 0; r < 8; r++) acc += sRE[e * 8 + r] * sRw1[r * 64 + h];
            sHid[idx] = silu_f(acc * 0.35355339059327373f);
        }
        __syncthreads();

        // w = (hid @ Rw2)/8 : register blocked 4 edges x 4 outputs per thread
        {
            int oq = t & 63, eg = t >> 6;
            float acc[4][4];
            #pragma unroll
            for (int j = 0; j < 4; j++)
                #pragma unroll
                for (int v = 0; v < 4; v++) acc[j][v] = 0.f;
            #pragma unroll 4
            for (int m = 0; m < 64; m++) {
                float4 r2 = *(const float4*)&sRw2[m * 256 + oq * 4];
                #pragma unroll
                for (int j = 0; j < 4; j++) {
                    float h = sHid[(eg + j * 4) * 64 + m];
                    acc[j][0] += h * r2.x; acc[j][1] += h * r2.y;
                    acc[j][2] += h * r2.z; acc[j][3] += h * r2.w;
                }
            }
            #pragma unroll
            for (int j = 0; j < 4; j++) {
                float4 o;
                o.x = acc[j][0] * 0.125f; o.y = acc[j][1] * 0.125f;
                o.z = acc[j][2] * 0.125f; o.w = acc[j][3] * 0.125f;
                *(float4*)&sW[(eg + j * 4) * 256 + oq * 4] = o;
            }
        }
        __syncthreads();

        // tensor product + scatter: 16 lanes per edge, 4 m's per lane
        {
            int g = t >> 4, l = t & 15, m4 = l * 4;
            int s = sSnd[g], r = sRcv[g];
            float y1x = sY[g * 4 + 0], y1y = sY[g * 4 + 1], y1z = sY[g * 4 + 2], y0 = sY[g * 4 + 3];
            float4 s0 = *(const float4*)&g_h0[s * 64  + m4];
            float4 sx = *(const float4*)&g_h1[s * 192 + 0   + m4];
            float4 sy = *(const float4*)&g_h1[s * 192 + 64  + m4];
            float4 sz = *(const float4*)&g_h1[s * 192 + 128 + m4];
            float4 w0 = *(const float4*)&sW[g * 256 + 0   + m4];
            float4 w1 = *(const float4*)&sW[g * 256 + 64  + m4];
            float4 w2 = *(const float4*)&sW[g * 256 + 128 + m4];
            float4 w3 = *(const float4*)&sW[g * 256 + 192 + m4];
            const float cN = 0.25f;  // 1/sqrt(avg_neigh=16)
            const float* S0 = (const float*)&s0; const float* SX = (const float*)&sx;
            const float* SY = (const float*)&sy; const float* SZ = (const float*)&sz;
            const float* W0 = (const float*)&w0; const float* W1 = (const float*)&w1;
            const float* W2 = (const float*)&w2; const float* W3 = (const float*)&w3;
            float A0[4], B0[4], AX[4], AY[4], AZ[4], BX[4], BY[4], BZ[4];
            #pragma unroll
            for (int i = 0; i < 4; i++) {
                float dd = SX[i] * y1x + SY[i] * y1y + SZ[i] * y1z;
                float w2s = cN * W2[i] * S0[i];
                A0[i] = cN * W0[i] * S0[i] * y0;
                B0[i] = cN * W1[i] * dd * SQRT3_INV;
                AX[i] = w2s * y1x; AY[i] = w2s * y1y; AZ[i] = w2s * y1z;
                BX[i] = cN * W3[i] * SX[i] * y0;
                BY[i] = cN * W3[i] * SY[i] * y0;
                BZ[i] = cN * W3[i] * SZ[i] * y0;
            }
            float* a0b = g_a0 + (size_t)r * 128;
            float* a1b = g_a1 + (size_t)r * 384;
            red4(a0b + m4,       A0[0], A0[1], A0[2], A0[3]);
            red4(a0b + 64 + m4,  B0[0], B0[1], B0[2], B0[3]);
            red4(a1b + 0   + m4, AX[0], AX[1], AX[2], AX[3]);
            red4(a1b + 64  + m4, BX[0], BX[1], BX[2], BX[3]);
            red4(a1b + 128 + m4, AY[0], AY[1], AY[2], AY[3]);
            red4(a1b + 192 + m4, BY[0], BY[1], BY[2], BY[3]);
            red4(a1b + 256 + m4, AZ[0], AZ[1], AZ[2], AZ[3]);
            red4(a1b + 320 + m4, BZ[0], BZ[1], BZ[2], BZ[3]);
        }
        __syncthreads();
    }
}

// ---------------- K4a: linear_down ------------------------------------------
// smem floats: sWd0[0,16384) sWd1[16384,24576) sA0[24576,25600) sA1[25600,28672)
#define K4A_SMEM_BYTES (28672 * 4)

__global__ void k_lin_down(const float* __restrict__ Wd0, const float* __restrict__ Wd1) {
    extern __shared__ float sm[];
    float* sWd0 = sm;
    float* sWd1 = sm + 16384;
    float* sA0  = sm + 24576;
    float* sA1  = sm + 25600;
    int t = threadIdx.x;
    for (int i = t; i < 16384; i += 256) sWd0[i] = Wd0[i];
    for (int i = t; i < 8192;  i += 256) sWd1[i] = Wd1[i];
    const float inv2 = 0.08838834764831845f;  // 1/sqrt(128)
    int ntile = NN / 8;
    for (int tile = blockIdx.x; tile < ntile; tile += gridDim.x) {
        int nb = tile * 8;
        for (int i = t; i < 1024; i += 256) sA0[i] = g_a0[nb * 128 + i];
        for (int i = t; i < 3072; i += 256) sA1[i] = g_a1[nb * 384 + i];
        __syncthreads();
        // d0 = a0 @ Wd0 * inv2
        {
            int k = t & 127, nh = t >> 7;
            float acc[4] = {0.f, 0.f, 0.f, 0.f};
            #pragma unroll 4
            for (int m = 0; m < 128; m++) {
                float w = sWd0[m * 128 + k];
                #pragma unroll
                for (int j = 0; j < 4; j++) acc[j] += sA0[(nh + 2 * j) * 128 + m] * w;
            }
            #pragma unroll
            for (int j = 0; j < 4; j++) g_d0[(nb + nh + 2 * j) * 128 + k] = acc[j] * inv2;
        }
        // d1[n][c][k] = sum_m a1[n][c][m]*Wd1[m][k]*inv2
        {
            int k = t & 63, u = t >> 6;
            if (u < 3) {
                int c = u;
                float acc[8] = {0.f,0.f,0.f,0.f,0.f,0.f,0.f,0.f};
                #pragma unroll 4
                for (int m = 0; m < 128; m++) {
                    float w = sWd1[m * 64 + k];
                    #pragma unroll
                    for (int j = 0; j < 8; j++) acc[j] += sA1[j * 384 + c * 128 + m] * w;
                }
                #pragma unroll
                for (int j = 0; j < 8; j++) g_d1[(nb + j) * 192 + c * 64 + k] = acc[j] * inv2;
            }
        }
        __syncthreads();
    }
}

// ---------------- K4b: species self-connection + gate + output --------------
// smem floats: sW0[0,32768) sW1[32768,49152) sX0[49152,49408) sX1[49408,50176)
#define K4B_SMEM_BYTES (50176 * 4)

__global__ void k_self_gate(const float* __restrict__ x0, const float* __restrict__ x1,
                            const int* __restrict__ species,
                            const float* __restrict__ Wsc0, const float* __restrict__ Wsc1,
                            float* __restrict__ out) {
    extern __shared__ float sm[];
    float* sW0 = sm;
    float* sW1 = sm + 32768;
    float* sX0 = sm + 49152;
    float* sX1 = sm + 49408;
    int t = threadIdx.x;
    for (int i = t; i < 32768; i += 256) sW0[i] = Wsc0[i];
    for (int i = t; i < 16384; i += 256) sW1[i] = Wsc1[i];
    float* outv = out + (size_t)NN * 64;
    int ng = NN / 4;
    for (int gId = blockIdx.x; gId < ng; gId += gridDim.x) {
        int nb = gId * 4;
        sX0[t] = x0[nb * 64 + t];
        for (int i = t; i < 768; i += 256) sX1[i] = x1[nb * 192 + i];
        __syncthreads();
        int ln = t >> 6, k = t & 63;
        int n = nb + ln;
        int sp = species[n];
        const float* w0 = sW0 + sp * 8192;
        const float* w1 = sW1 + sp * 4096;
        float aA = 0.f, aB = 0.f, c0 = 0.f, c1 = 0.f, c2 = 0.f;
        #pragma unroll 8
        for (int m = 0; m < 64; m++) {
            float xv = sX0[ln * 64 + m];
            aA += xv * w0[m * 128 + k];
            aB += xv * w0[m * 128 + 64 + k];
            float vx = sX1[ln * 192 + m * 3 + 0];
            float vy = sX1[ln * 192 + m * 3 + 1];
            float vz = sX1[ln * 192 + m * 3 + 2];
            float wm = w1[m * 64 + k];
            c0 += vx * wm; c1 += vy * wm; c2 += vz * wm;
        }
        const float inv = 0.125f;  // 1/sqrt(MUL)
        float f0a = 0.5f * (g_d0[n * 128 + k]      + aA * inv);
        float f0b = 0.5f * (g_d0[n * 128 + 64 + k] + aB * inv);
        float scal = silu_f(f0a);
        float gate = silu_f(f0b);
        out[(size_t)n * 64 + k] = scal;
        float v0 = 0.5f * (g_d1[n * 192 + 0   + k] + c0 * inv) * gate;
        float v1 = 0.5f * (g_d1[n * 192 + 64  + k] + c1 * inv) * gate;
        float v2 = 0.5f * (g_d1[n * 192 + 128 + k] + c2 * inv) * gate;
        outv[(size_t)n * 192 + k * 3 + 0] = v0;
        outv[(size_t)n * 192 + k * 3 + 1] = v1;
        outv[(size_t)n * 192 + k * 3 + 2] = v2;
        __syncthreads();
    }
}

// ---------------- launch -----------------------------------------------------
extern "C" void kernel_launch(void* const* d_in, const int* in_sizes, int n_in,
                              void* d_out, int out_size) {
    const float* x0   = (const float*)d_in[0];
    const float* x1   = (const float*)d_in[1];
    const float* ey0  = (const float*)d_in[2];
    const float* ey1  = (const float*)d_in[3];
    const float* re   = (const float*)d_in[4];
    const int*   snd  = (const int*)d_in[5];
    const int*   rcv  = (const int*)d_in[6];
    const int*   spc  = (const int*)d_in[7];
    const float* Wup0 = (const float*)d_in[8];
    const float* Wup1 = (const float*)d_in[9];
    const float* Rw1  = (const float*)d_in[10];
    const float* Rw2  = (const float*)d_in[11];
    const float* Wd0  = (const float*)d_in[12];
    const float* Wd1  = (const float*)d_in[13];
    const float* Wsc0 = (const float*)d_in[14];
    const float* Wsc1 = (const float*)d_in[15];
    float* out = (float*)d_out;

    cudaFuncSetAttribute(k_edge,      cudaFuncAttributeMaxDynamicSharedMemorySize, K3_SMEM_BYTES);
    cudaFuncSetAttribute(k_lin_down,  cudaFuncAttributeMaxDynamicSharedMemorySize, K4A_SMEM_BYTES);
    cudaFuncSetAttribute(k_self_gate, cudaFuncAttributeMaxDynamicSharedMemorySize, K4B_SMEM_BYTES);

    k_zero<<<2048, 256>>>();
    k_linear_up<<<NN / 16, 256>>>(x0, x1, Wup0, Wup1);
    k_edge<<<1024, 256, K3_SMEM_BYTES>>>(re, ey0, ey1, snd, rcv, Rw1, Rw2);
    k_lin_down<<<592, 256, K4A_SMEM_BYTES>>>(Wd0, Wd1);
    k_self_gate<<<148, 256, K4B_SMEM_BYTES>>>(x0, x1, spc, Wsc0, Wsc1, out);
}

// round 8
// speedup vs baseline: 1.2170x; 1.2170x over previous
#include <cuda_runtime.h>
#include <cuda_bf16.h>
#include <math.h>
#include <stdint.h>

#define NN 16384
#define EE 262144
#define SQRT3_INV 0.5773502691896258f

// ---------------- device scratch ------------------------------------------
__device__ __align__(16) float g_h0[NN * 64];    // [n][k]
__device__ __align__(16) float g_h1[NN * 192];   // [n][c][k]
__device__ __align__(16) float g_a0[NN * 128];   // [n][2*MUL]
__device__ __align__(16) float g_a1[NN * 384];   // [n][c][128]
__device__ __align__(16) float g_d0[NN * 128];
__device__ __align__(16) float g_d1[NN * 192];

__device__ __forceinline__ float silu_f(float x) { return x / (1.0f + expf(-x)); }

__device__ __forceinline__ void red4(float* p, float a, float b, float c, float d) {
    asm volatile("red.global.add.v4.f32 [%0], {%1,%2,%3,%4};"
                 :: "l"(p), "f"(a), "f"(b), "f"(c), "f"(d) : "memory");
}

// m16n8k16 row.col bf16 -> f32, accumulate in place
__device__ __forceinline__ void mma_bf16(float* d, uint32_t a0, uint32_t a1,
                                         uint32_t a2, uint32_t a3,
                                         uint32_t b0, uint32_t b1) {
    asm volatile(
        "mma.sync.aligned.m16n8k16.row.col.f32.bf16.bf16.f32 "
        "{%0,%1,%2,%3}, {%4,%5,%6,%7}, {%8,%9}, {%0,%1,%2,%3};"
        : "+f"(d[0]), "+f"(d[1]), "+f"(d[2]), "+f"(d[3])
        : "r"(a0), "r"(a1), "r"(a2), "r"(a3), "r"(b0), "r"(b1));
}

// ---------------- K1: linear_up ---------------------------------------------
__global__ void k_linear_up(const float* __restrict__ x0, const float* __restrict__ x1,
                            const float* __restrict__ Wup0, const float* __restrict__ Wup1) {
    __shared__ float sW0[4096];
    __shared__ float sW1[4096];
    __shared__ float sX0[16 * 64];
    __shared__ float sX1[16 * 192];
    int t = threadIdx.x;
    for (int i = t; i < 4096; i += 256) { sW0[i] = Wup0[i]; sW1[i] = Wup1[i]; }
    int nb = blockIdx.x * 16;
    for (int i = t; i < 16 * 64;  i += 256) sX0[i] = x0[nb * 64  + i];
    for (int i = t; i < 16 * 192; i += 256) sX1[i] = x1[nb * 192 + i];
    __syncthreads();
    int k = t & 63, q = t >> 6;
    const float inv = 0.125f;
    if (q == 0) {
        for (int n = 0; n < 16; n++) {
            float acc = 0.f;
            #pragma unroll 16
            for (int m = 0; m < 64; m++) acc += sX0[n * 64 + m] * sW0[m * 64 + k];
            g_h0[(nb + n) * 64 + k] = acc * inv;
        }
    } else {
        int c = q - 1;
        for (int n = 0; n < 16; n++) {
            float acc = 0.f;
            #pragma unroll 16
            for (int m = 0; m < 64; m++) acc += sX1[n * 192 + m * 3 + c] * sW1[m * 64 + k];
            g_h1[(nb + n) * 192 + c * 64 + k] = acc * inv;
        }
    }
}

// ---------------- K2: zero accumulators ------------------------------------
__global__ void k_zero() {
    float4 z = make_float4(0.f, 0.f, 0.f, 0.f);
    float4* p0 = (float4*)g_a0;
    float4* p1 = (float4*)g_a1;
    int stride = gridDim.x * blockDim.x;
    for (int i = blockIdx.x * blockDim.x + threadIdx.x; i < NN * 32; i += stride) p0[i] = z;
    for (int i = blockIdx.x * blockDim.x + threadIdx.x; i < NN * 96; i += stride) p1[i] = z;
}

// ---------------- K3: fused radial MLP (mma.sync bf16x3) + TP + scatter ----
// smem layout in bytes; A/B tiles are bf16 with row stride 72 elements (144 B)
#define K3_AHI  0
#define K3_ALO  (K3_AHI + 128 * 144)          // 18432
#define K3_BHI  (K3_ALO + 128 * 144)          // 36864
#define K3_BLO  (K3_BHI + 256 * 144)          // 73728
#define K3_RE   (K3_BLO + 256 * 144)          // 110592
#define K3_Y    (K3_RE + 4096)                // 114688
#define K3_SND  (K3_Y + 2048)                 // 116736
#define K3_RCV  (K3_SND + 512)                // 117248
#define K3_RW1  (K3_RCV + 512)                // 117760
#define K3_SMEM_BYTES (K3_RW1 + 2048)         // 119808

__global__ void __launch_bounds__(256, 1)
k_edge(const float* __restrict__ re, const float* __restrict__ y0v,
       const float* __restrict__ y1v, const int* __restrict__ snd,
       const int* __restrict__ rcv,
       const float* __restrict__ Rw1, const float* __restrict__ Rw2) {
    extern __shared__ char smc[];
    float* sRE  = (float*)(smc + K3_RE);
    float* sY   = (float*)(smc + K3_Y);
    int*   sSnd = (int*)(smc + K3_SND);
    int*   sRcv = (int*)(smc + K3_RCV);
    float* sRw1 = (float*)(smc + K3_RW1);

    int t = threadIdx.x;
    int wid = t >> 5, l = t & 31;
    int r = l >> 2, p = l & 3;

    // ---- stage B = Rw2^T [256 n][64 k], column-permuted, bf16 hi/lo -------
    // orig col n = 16b + 4p' + j2  ->  slot = 16b + 2p' + (j2&1) + 8*(j2>>1)
    for (int i = t; i < 16384; i += 256) {
        int n = i >> 6, k = i & 63;
        int b = n >> 4, q = n & 15;
        int pp = q >> 2, j2 = q & 3;
        int slot = (b << 4) + 2 * pp + (j2 & 1) + ((j2 >> 1) << 3);
        float v = Rw2[k * 256 + n];
        __nv_bfloat16 hi = __float2bfloat16(v);
        __nv_bfloat16 lo = __float2bfloat16(v - __bfloat162float(hi));
        *(uint16_t*)(smc + K3_BHI + (slot * 72 + k) * 2) = *(uint16_t*)&hi;
        *(uint16_t*)(smc + K3_BLO + (slot * 72 + k) * 2) = *(uint16_t*)&lo;
    }
    for (int i = t; i < 512; i += 256) sRw1[i] = Rw1[i];
    __syncthreads();

    const float cN = 0.03125f;  // 1/sqrt(16) * 1/sqrt(64)
    const int ntile = EE / 128;
    for (int ch = blockIdx.x; ch < ntile; ch += gridDim.x) {
        int e0 = ch * 128;
        // ---- stage edge data ----
        for (int i = t; i < 1024; i += 256) sRE[i] = re[e0 * 8 + i];
        if (t < 128) {
            sSnd[t] = snd[e0 + t];
            sRcv[t] = rcv[e0 + t];
            sY[t * 4 + 3] = y0v[e0 + t];
        }
        for (int i = t; i < 384; i += 256) sY[(i / 3) * 4 + (i % 3)] = y1v[e0 * 3 + i];
        __syncthreads();

        // ---- hidden layer -> A tiles (bf16 hi/lo) ----
        #pragma unroll 4
        for (int j = 0; j < 32; j++) {
            int idx = t + j * 256;
            int e = idx >> 6, h = idx & 63;
            float acc = 0.f;
            #pragma unroll
            for (int rr = 0; rr < 8; rr++) acc += sRE[e * 8 + rr] * sRw1[rr * 64 + h];
            float v = silu_f(acc * 0.35355339059327373f);
            __nv_bfloat16 hi = __float2bfloat16(v);
            __nv_bfloat16 lo = __float2bfloat16(v - __bfloat162float(hi));
            *(uint16_t*)(smc + K3_AHI + (e * 72 + h) * 2) = *(uint16_t*)&hi;
            *(uint16_t*)(smc + K3_ALO + (e * 72 + h) * 2) = *(uint16_t*)&lo;
        }
        __syncthreads();

        // ---- load A fragments for this warp's 16 edges (all 4 k-steps) ----
        uint32_t ah[4][4], al[4][4];
        {
            int rowb = (wid * 16 + r) * 72;
            #pragma unroll
            for (int k = 0; k < 4; k++) {
                int kb = k * 16 + 2 * p;
                ah[k][0] = *(const uint32_t*)(smc + K3_AHI + (rowb + kb) * 2);
                ah[k][1] = *(const uint32_t*)(smc + K3_AHI + (rowb + 8 * 72 + kb) * 2);
                ah[k][2] = *(const uint32_t*)(smc + K3_AHI + (rowb + kb + 8) * 2);
                ah[k][3] = *(const uint32_t*)(smc + K3_AHI + (rowb + 8 * 72 + kb + 8) * 2);
                al[k][0] = *(const uint32_t*)(smc + K3_ALO + (rowb + kb) * 2);
                al[k][1] = *(const uint32_t*)(smc + K3_ALO + (rowb + 8 * 72 + kb) * 2);
                al[k][2] = *(const uint32_t*)(smc + K3_ALO + (rowb + kb + 8) * 2);
                al[k][3] = *(const uint32_t*)(smc + K3_ALO + (rowb + 8 * 72 + kb + 8) * 2);
            }
        }

        // ---- 4 chunks: MMA (8 subtiles x 4 k x 3 products) + TP + scatter --
        #pragma unroll
        for (int jc = 0; jc < 4; jc++) {
            float c[8][4];
            #pragma unroll
            for (int s = 0; s < 8; s++) { c[s][0] = c[s][1] = c[s][2] = c[s][3] = 0.f; }

            #pragma unroll
            for (int s = 0; s < 4; s++) {
                #pragma unroll
                for (int tb = 0; tb < 2; tb++) {
                    int tile = 8 * s + 2 * jc + tb;
                    int nrow = (tile * 8 + r) * 72;
                    float* cc = c[s * 2 + tb];
                    #pragma unroll
                    for (int k = 0; k < 4; k++) {
                        int kb = k * 16 + 2 * p;
                        uint32_t bh0 = *(const uint32_t*)(smc + K3_BHI + (nrow + kb) * 2);
                        uint32_t bh1 = *(const uint32_t*)(smc + K3_BHI + (nrow + kb + 8) * 2);
                        uint32_t bl0 = *(const uint32_t*)(smc + K3_BLO + (nrow + kb) * 2);
                        uint32_t bl1 = *(const uint32_t*)(smc + K3_BLO + (nrow + kb + 8) * 2);
                        mma_bf16(cc, ah[k][0], ah[k][1], ah[k][2], ah[k][3], bh0, bh1);
                        mma_bf16(cc, ah[k][0], ah[k][1], ah[k][2], ah[k][3], bl0, bl1);
                        mma_bf16(cc, al[k][0], al[k][1], al[k][2], al[k][3], bh0, bh1);
                    }
                }
            }

            // ---- TP + scatter for this chunk's m-range ----
            int m0 = 16 * jc + 4 * p;
            #pragma unroll
            for (int rr = 0; rr < 2; rr++) {
                int e = wid * 16 + r + rr * 8;
                int sn = sSnd[e], rc = sRcv[e];
                float y1x = sY[e * 4 + 0], y1y = sY[e * 4 + 1];
                float y1z = sY[e * 4 + 2], y0 = sY[e * 4 + 3];
                const float* h0p = g_h0 + (size_t)sn * 64 + m0;
                const float* h1p = g_h1 + (size_t)sn * 192 + m0;
                float4 s0 = *(const float4*)h0p;
                float4 sx = *(const float4*)h1p;
                float4 sy = *(const float4*)(h1p + 64);
                float4 sz = *(const float4*)(h1p + 128);
                int o = rr * 2;
                float W0[4] = {c[0][o], c[0][o + 1], c[1][o], c[1][o + 1]};
                float W1[4] = {c[2][o], c[2][o + 1], c[3][o], c[3][o + 1]};
                float W2[4] = {c[4][o], c[4][o + 1], c[5][o], c[5][o + 1]};
                float W3[4] = {c[6][o], c[6][o + 1], c[7][o], c[7][o + 1]};
                const float* S0 = (const float*)&s0;
                const float* SX = (const float*)&sx;
                const float* SYv = (const float*)&sy;
                const float* SZ = (const float*)&sz;
                float A0[4], B0[4], AX[4], AY[4], AZ[4], BX[4], BY[4], BZ[4];
                #pragma unroll
                for (int i = 0; i < 4; i++) {
                    float dd = SX[i] * y1x + SYv[i] * y1y + SZ[i] * y1z;
                    A0[i] = cN * W0[i] * S0[i] * y0;
                    B0[i] = cN * W1[i] * dd * SQRT3_INV;
                    float t2 = cN * W2[i] * S0[i];
                    AX[i] = t2 * y1x; AY[i] = t2 * y1y; AZ[i] = t2 * y1z;
                    float t3 = cN * W3[i] * y0;
                    BX[i] = t3 * SX[i]; BY[i] = t3 * SYv[i]; BZ[i] = t3 * SZ[i];
                }
                float* a0b = g_a0 + (size_t)rc * 128 + m0;
                float* a1b = g_a1 + (size_t)rc * 384 + m0;
                red4(a0b,       A0[0], A0[1], A0[2], A0[3]);
                red4(a0b + 64,  B0[0], B0[1], B0[2], B0[3]);
                red4(a1b,       AX[0], AX[1], AX[2], AX[3]);
                red4(a1b + 64,  BX[0], BX[1], BX[2], BX[3]);
                red4(a1b + 128, AY[0], AY[1], AY[2], AY[3]);
                red4(a1b + 192, BY[0], BY[1], BY[2], BY[3]);
                red4(a1b + 256, AZ[0], AZ[1], AZ[2], AZ[3]);
                red4(a1b + 320, BZ[0], BZ[1], BZ[2], BZ[3]);
            }
        }
        __syncthreads();
    }
}

// ---------------- K4a: linear_down (broadcast-blocked, 32-node tiles) -------
#define K4A_SMEM_BYTES (40960 * 4)

__global__ void __launch_bounds__(256, 1)
k_lin_down(const float* __restrict__ Wd0, const float* __restrict__ Wd1) {
    extern __shared__ float sm[];
    float* sWd0 = sm;
    float* sWd1 = sm + 16384;
    float* sA0  = sm + 24576;
    float* sA1  = sm + 28672;
    int t = threadIdx.x;
    for (int i = t; i < 4096; i += 256) ((float4*)sWd0)[i] = ((const float4*)Wd0)[i];
    for (int i = t; i < 2048; i += 256) ((float4*)sWd1)[i] = ((const float4*)Wd1)[i];
    const float inv2 = 0.08838834764831845f;  // 1/sqrt(128)
    int w = t >> 5, l = t & 31;
    const int ntile = NN / 32;
    for (int tile = blockIdx.x; tile < ntile; tile += gridDim.x) {
        int nb = tile * 32;
        for (int i = t; i < 1024; i += 256) ((float4*)sA0)[i] = ((const float4*)(g_a0 + (size_t)nb * 128))[i];
        for (int i = t; i < 3072; i += 256) ((float4*)sA1)[i] = ((const float4*)(g_a1 + (size_t)nb * 384))[i];
        __syncthreads();
        // d0: warp w -> nodes w*4..w*4+3, lane -> k4 = l*4
        {
            int k4 = l * 4;
            float acc[4][4];
            #pragma unroll
            for (int j = 0; j < 4; j++) { acc[j][0] = acc[j][1] = acc[j][2] = acc[j][3] = 0.f; }
            #pragma unroll 4
            for (int m = 0; m < 128; m++) {
                float4 wv = *(const float4*)&sWd0[m * 128 + k4];
                #pragma unroll
                for (int j = 0; j < 4; j++) {
                    float a = sA0[(w * 4 + j) * 128 + m];
                    acc[j][0] += a * wv.x; acc[j][1] += a * wv.y;
                    acc[j][2] += a * wv.z; acc[j][3] += a * wv.w;
                }
            }
            #pragma unroll
            for (int j = 0; j < 4; j++) {
                float4 o = make_float4(acc[j][0] * inv2, acc[j][1] * inv2,
                                       acc[j][2] * inv2, acc[j][3] * inv2);
                *(float4*)&g_d0[(size_t)(nb + w * 4 + j) * 128 + k4] = o;
            }
        }
        // d1: units u = w + rep*8 -> c = u%3, node group = u/3
        #pragma unroll
        for (int rep = 0; rep < 3; rep++) {
            int u = w + rep * 8;
            int c = u % 3, gg = u / 3;
            int k2 = l * 2;
            float acc[4][2];
            #pragma unroll
            for (int j = 0; j < 4; j++) { acc[j][0] = acc[j][1] = 0.f; }
            #pragma unroll 4
            for (int m = 0; m < 128; m++) {
                float2 wv = *(const float2*)&sWd1[m * 64 + k2];
                #pragma unroll
                for (int j = 0; j < 4; j++) {
                    float a = sA1[(gg * 4 + j) * 384 + c * 128 + m];
                    acc[j][0] += a * wv.x; acc[j][1] += a * wv.y;
                }
            }
            #pragma unroll
            for (int j = 0; j < 4; j++) {
                float2 o = make_float2(acc[j][0] * inv2, acc[j][1] * inv2);
                *(float2*)&g_d1[(size_t)(nb + gg * 4 + j) * 192 + c * 64 + k2] = o;
            }
        }
        __syncthreads();
    }
}

// ---------------- K4b: species self-connection + gate + output --------------
#define K4B_SMEM_BYTES (50176 * 4)

__global__ void k_self_gate(const float* __restrict__ x0, const float* __restrict__ x1,
                            const int* __restrict__ species,
                            const float* __restrict__ Wsc0, const float* __restrict__ Wsc1,
                            float* __restrict__ out) {
    extern __shared__ float sm[];
    float* sW0 = sm;
    float* sW1 = sm + 32768;
    float* sX0 = sm + 49152;
    float* sX1 = sm + 49408;
    int t = threadIdx.x;
    for (int i = t; i < 32768; i += 256) sW0[i] = Wsc0[i];
    for (int i = t; i < 16384; i += 256) sW1[i] = Wsc1[i];
    float* outv = out + (size_t)NN * 64;
    int ng = NN / 4;
    for (int gId = blockIdx.x; gId < ng; gId += gridDim.x) {
        int nb = gId * 4;
        sX0[t] = x0[nb * 64 + t];
        for (int i = t; i < 768; i += 256) sX1[i] = x1[nb * 192 + i];
        __syncthreads();
        int ln = t >> 6, k = t & 63;
        int n = nb + ln;
        int sp = species[n];
        const float* w0 = sW0 + sp * 8192;
        const float* w1 = sW1 + sp * 4096;
        float aA = 0.f, aB = 0.f, c0 = 0.f, c1 = 0.f, c2 = 0.f;
        #pragma unroll 8
        for (int m = 0; m < 64; m++) {
            float xv = sX0[ln * 64 + m];
            aA += xv * w0[m * 128 + k];
            aB += xv * w0[m * 128 + 64 + k];
            float vx = sX1[ln * 192 + m * 3 + 0];
            float vy = sX1[ln * 192 + m * 3 + 1];
            float vz = sX1[ln * 192 + m * 3 + 2];
            float wm = w1[m * 64 + k];
            c0 += vx * wm; c1 += vy * wm; c2 += vz * wm;
        }
        const float inv = 0.125f;
        float f0a = 0.5f * (g_d0[n * 128 + k]      + aA * inv);
        float f0b = 0.5f * (g_d0[n * 128 + 64 + k] + aB * inv);
        float scal = silu_f(f0a);
        float gate = silu_f(f0b);
        out[(size_t)n * 64 + k] = scal;
        float v0 = 0.5f * (g_d1[n * 192 + 0   + k] + c0 * inv) * gate;
        float v1 = 0.5f * (g_d1[n * 192 + 64  + k] + c1 * inv) * gate;
        float v2 = 0.5f * (g_d1[n * 192 + 128 + k] + c2 * inv) * gate;
        outv[(size_t)n * 192 + k * 3 + 0] = v0;
        outv[(size_t)n * 192 + k * 3 + 1] = v1;
        outv[(size_t)n * 192 + k * 3 + 2] = v2;
        __syncthreads();
    }
}

// ---------------- launch -----------------------------------------------------
extern "C" void kernel_launch(void* const* d_in, const int* in_sizes, int n_in,
                              void* d_out, int out_size) {
    const float* x0   = (const float*)d_in[0];
    const float* x1   = (const float*)d_in[1];
    const float* ey0  = (const float*)d_in[2];
    const float* ey1  = (const float*)d_in[3];
    const float* re   = (const float*)d_in[4];
    const int*   snd  = (const int*)d_in[5];
    const int*   rcv  = (const int*)d_in[6];
    const int*   spc  = (const int*)d_in[7];
    const float* Wup0 = (const float*)d_in[8];
    const float* Wup1 = (const float*)d_in[9];
    const float* Rw1  = (const float*)d_in[10];
    const float* Rw2  = (const float*)d_in[11];
    const float* Wd0  = (const float*)d_in[12];
    const float* Wd1  = (const float*)d_in[13];
    const float* Wsc0 = (const float*)d_in[14];
    const float* Wsc1 = (const float*)d_in[15];
    float* out = (float*)d_out;

    cudaFuncSetAttribute(k_edge,      cudaFuncAttributeMaxDynamicSharedMemorySize, K3_SMEM_BYTES);
    cudaFuncSetAttribute(k_lin_down,  cudaFuncAttributeMaxDynamicSharedMemorySize, K4A_SMEM_BYTES);
    cudaFuncSetAttribute(k_self_gate, cudaFuncAttributeMaxDynamicSharedMemorySize, K4B_SMEM_BYTES);

    k_zero<<<2048, 256>>>();
    k_linear_up<<<NN / 16, 256>>>(x0, x1, Wup0, Wup1);
    k_edge<<<148, 256, K3_SMEM_BYTES>>>(re, ey0, ey1, snd, rcv, Rw1, Rw2);
    k_lin_down<<<148, 256, K4A_SMEM_BYTES>>>(Wd0, Wd1);
    k_self_gate<<<148, 256, K4B_SMEM_BYTES>>>(x0, x1, spc, Wsc0, Wsc1, out);
}

// round 10
// speedup vs baseline: 1.2967x; 1.0655x over previous
#include <cuda_runtime.h>
#include <cuda_bf16.h>
#include <math.h>
#include <stdint.h>

#define NN 16384
#define EE 262144
#define SQRT3_INV 0.5773502691896258f

// ---------------- device scratch ------------------------------------------
__device__ __align__(16) float g_h0[NN * 64];    // [n][k]
__device__ __align__(16) float g_h1[NN * 192];   // [n][c][k]
__device__ __align__(16) float g_a0[NN * 128];   // [n][2*MUL]
__device__ __align__(16) float g_a1[NN * 384];   // [n][c][128]
__device__ __align__(16) float g_d0[NN * 128];
__device__ __align__(16) float g_d1[NN * 192];

__device__ __forceinline__ float silu_f(float x) { return x / (1.0f + expf(-x)); }

__device__ __forceinline__ void red4(float* p, float a, float b, float c, float d) {
    asm volatile("red.global.add.v4.f32 [%0], {%1,%2,%3,%4};"
                 :: "l"(p), "f"(a), "f"(b), "f"(c), "f"(d) : "memory");
}

// m16n8k16 row.col bf16 -> f32, accumulate in place
__device__ __forceinline__ void mma_bf16(float* d, uint32_t a0, uint32_t a1,
                                         uint32_t a2, uint32_t a3,
                                         uint32_t b0, uint32_t b1) {
    asm volatile(
        "mma.sync.aligned.m16n8k16.row.col.f32.bf16.bf16.f32 "
        "{%0,%1,%2,%3}, {%4,%5,%6,%7}, {%8,%9}, {%0,%1,%2,%3};"
        : "+f"(d[0]), "+f"(d[1]), "+f"(d[2]), "+f"(d[3])
        : "r"(a0), "r"(a1), "r"(a2), "r"(a3), "r"(b0), "r"(b1));
}

// ---------------- K1: linear_up ---------------------------------------------
__global__ void k_linear_up(const float* __restrict__ x0, const float* __restrict__ x1,
                            const float* __restrict__ Wup0, const float* __restrict__ Wup1) {
    __shared__ float sW0[4096];
    __shared__ float sW1[4096];
    __shared__ float sX0[16 * 64];
    __shared__ float sX1[16 * 192];
    int t = threadIdx.x;
    for (int i = t; i < 4096; i += 256) { sW0[i] = Wup0[i]; sW1[i] = Wup1[i]; }
    int nb = blockIdx.x * 16;
    for (int i = t; i < 16 * 64;  i += 256) sX0[i] = x0[nb * 64  + i];
    for (int i = t; i < 16 * 192; i += 256) sX1[i] = x1[nb * 192 + i];
    __syncthreads();
    int k = t & 63, q = t >> 6;
    const float inv = 0.125f;
    if (q == 0) {
        for (int n = 0; n < 16; n++) {
            float acc = 0.f;
            #pragma unroll 16
            for (int m = 0; m < 64; m++) acc += sX0[n * 64 + m] * sW0[m * 64 + k];
            g_h0[(nb + n) * 64 + k] = acc * inv;
        }
    } else {
        int c = q - 1;
        for (int n = 0; n < 16; n++) {
            float acc = 0.f;
            #pragma unroll 16
            for (int m = 0; m < 64; m++) acc += sX1[n * 192 + m * 3 + c] * sW1[m * 64 + k];
            g_h1[(nb + n) * 192 + c * 64 + k] = acc * inv;
        }
    }
}

// ---------------- K2: zero accumulators ------------------------------------
__global__ void k_zero() {
    float4 z = make_float4(0.f, 0.f, 0.f, 0.f);
    float4* p0 = (float4*)g_a0;
    float4* p1 = (float4*)g_a1;
    int stride = gridDim.x * blockDim.x;
    for (int i = blockIdx.x * blockDim.x + threadIdx.x; i < NN * 32; i += stride) p0[i] = z;
    for (int i = blockIdx.x * blockDim.x + threadIdx.x; i < NN * 96; i += stride) p1[i] = z;
}

// ---------------- K3: fused radial MLP (mma bf16x3) + TP + scatter ---------
// m-split: CTA parity q owns output chunks jc = 2q, 2q+1 (m in [32q, 32q+32)
// within each of the 4 w-groups). B tile holds only that half: 128 rows.
#define K3_BHI  0
#define K3_BLO  18432
#define K3_AHI  36864
#define K3_ALO  55296
#define K3_RE   73728
#define K3_Y    77824
#define K3_SND  79872
#define K3_RCV  80384
#define K3_RW1  80896
#define K3_SMEM_BYTES 82944

__global__ void __launch_bounds__(256, 2)
k_edge(const float* __restrict__ re, const float* __restrict__ y0v,
       const float* __restrict__ y1v, const int* __restrict__ snd,
       const int* __restrict__ rcv,
       const float* __restrict__ Rw1, const float* __restrict__ Rw2) {
    extern __shared__ char smc[];
    float* sRE  = (float*)(smc + K3_RE);
    float* sY   = (float*)(smc + K3_Y);
    int*   sSnd = (int*)(smc + K3_SND);
    int*   sRcv = (int*)(smc + K3_RCV);
    float* sRw1 = (float*)(smc + K3_RW1);

    int t = threadIdx.x;
    int wid = t >> 5, l = t & 31;
    int r = l >> 2, p = l & 3;
    int q = blockIdx.x & 1;

    // ---- stage B = Rw2^T, column-permuted, HALF (this CTA's jc pair) -------
    for (int i = t; i < 16384; i += 256) {
        int n = i >> 6, k = i & 63;
        int b = n >> 4, qq = n & 15;
        int pp = qq >> 2, j2 = qq & 3;
        int slot = (b << 4) + 2 * pp + (j2 & 1) + ((j2 >> 1) << 3);
        if (((slot >> 5) & 1) != q) continue;       // keep only my jc pair
        int rloc = ((slot >> 6) << 5) + (((slot >> 3) & 3) << 3) + (slot & 7);
        float v = Rw2[k * 256 + n];
        __nv_bfloat16 hi = __float2bfloat16(v);
        __nv_bfloat16 lo = __float2bfloat16(v - __bfloat162float(hi));
        *(uint16_t*)(smc + K3_BHI + (rloc * 72 + k) * 2) = *(uint16_t*)&hi;
        *(uint16_t*)(smc + K3_BLO + (rloc * 72 + k) * 2) = *(uint16_t*)&lo;
    }
    for (int i = t; i < 512; i += 256) sRw1[i] = Rw1[i];
    __syncthreads();

    const float cN = 0.03125f;  // 1/sqrt(16) * 1/sqrt(64)
    const int step = gridDim.x >> 1;
    for (int ch = blockIdx.x >> 1; ch < EE / 128; ch += step) {
        int e0 = ch * 128;
        // ---- stage edge data ----
        for (int i = t; i < 1024; i += 256) sRE[i] = re[e0 * 8 + i];
        if (t < 128) {
            sSnd[t] = snd[e0 + t];
            sRcv[t] = rcv[e0 + t];
            sY[t * 4 + 3] = y0v[e0 + t];
        }
        for (int i = t; i < 384; i += 256) sY[(i / 3) * 4 + (i % 3)] = y1v[e0 * 3 + i];
        __syncthreads();

        // ---- hidden layer -> A tiles (bf16 hi/lo) ----
        #pragma unroll 4
        for (int j = 0; j < 32; j++) {
            int idx = t + j * 256;
            int e = idx >> 6, h = idx & 63;
            float acc = 0.f;
            #pragma unroll
            for (int rr = 0; rr < 8; rr++) acc += sRE[e * 8 + rr] * sRw1[rr * 64 + h];
            float v = silu_f(acc * 0.35355339059327373f);
            __nv_bfloat16 hi = __float2bfloat16(v);
            __nv_bfloat16 lo = __float2bfloat16(v - __bfloat162float(hi));
            *(uint16_t*)(smc + K3_AHI + (e * 72 + h) * 2) = *(uint16_t*)&hi;
            *(uint16_t*)(smc + K3_ALO + (e * 72 + h) * 2) = *(uint16_t*)&lo;
        }
        __syncthreads();

        // ---- load A fragments for this warp's 16 edges (all 4 k-steps) ----
        uint32_t ah[4][4], al[4][4];
        {
            int rowb = (wid * 16 + r) * 72;
            #pragma unroll
            for (int k = 0; k < 4; k++) {
                int kb = k * 16 + 2 * p;
                ah[k][0] = *(const uint32_t*)(smc + K3_AHI + (rowb + kb) * 2);
                ah[k][1] = *(const uint32_t*)(smc + K3_AHI + (rowb + 8 * 72 + kb) * 2);
                ah[k][2] = *(const uint32_t*)(smc + K3_AHI + (rowb + kb + 8) * 2);
                ah[k][3] = *(const uint32_t*)(smc + K3_AHI + (rowb + 8 * 72 + kb + 8) * 2);
                al[k][0] = *(const uint32_t*)(smc + K3_ALO + (rowb + kb) * 2);
                al[k][1] = *(const uint32_t*)(smc + K3_ALO + (rowb + 8 * 72 + kb) * 2);
                al[k][2] = *(const uint32_t*)(smc + K3_ALO + (rowb + kb + 8) * 2);
                al[k][3] = *(const uint32_t*)(smc + K3_ALO + (rowb + 8 * 72 + kb + 8) * 2);
            }
        }

        // ---- 2 local chunks: MMA (8 subtiles x 4 k x 3 products) + TP ------
        #pragma unroll
        for (int jc2 = 0; jc2 < 2; jc2++) {
            float c[8][4];
            #pragma unroll
            for (int s = 0; s < 8; s++) { c[s][0] = c[s][1] = c[s][2] = c[s][3] = 0.f; }

            #pragma unroll
            for (int s = 0; s < 4; s++) {
                #pragma unroll
                for (int tb = 0; tb < 2; tb++) {
                    int tloc = s * 4 + 2 * jc2 + tb;
                    int nrow = (tloc * 8 + r) * 72;
                    float* cc = c[s * 2 + tb];
                    #pragma unroll
                    for (int k = 0; k < 4; k++) {
                        int kb = k * 16 + 2 * p;
                        uint32_t bh0 = *(const uint32_t*)(smc + K3_BHI + (nrow + kb) * 2);
                        uint32_t bh1 = *(const uint32_t*)(smc + K3_BHI + (nrow + kb + 8) * 2);
                        uint32_t bl0 = *(const uint32_t*)(smc + K3_BLO + (nrow + kb) * 2);
                        uint32_t bl1 = *(const uint32_t*)(smc + K3_BLO + (nrow + kb + 8) * 2);
                        mma_bf16(cc, ah[k][0], ah[k][1], ah[k][2], ah[k][3], bh0, bh1);
                        mma_bf16(cc, ah[k][0], ah[k][1], ah[k][2], ah[k][3], bl0, bl1);
                        mma_bf16(cc, al[k][0], al[k][1], al[k][2], al[k][3], bh0, bh1);
                    }
                }
            }

            // ---- TP + scatter for this chunk's m-range ----
            int m0 = 16 * (2 * q + jc2) + 4 * p;
            #pragma unroll
            for (int rr = 0; rr < 2; rr++) {
                int e = wid * 16 + r + rr * 8;
                int sn = sSnd[e], rc = sRcv[e];
                float y1x = sY[e * 4 + 0], y1y = sY[e * 4 + 1];
                float y1z = sY[e * 4 + 2], y0 = sY[e * 4 + 3];
                const float* h0p = g_h0 + (size_t)sn * 64 + m0;
                const float* h1p = g_h1 + (size_t)sn * 192 + m0;
                float4 s0 = *(const float4*)h0p;
                float4 sx = *(const float4*)h1p;
                float4 sy = *(const float4*)(h1p + 64);
                float4 sz = *(const float4*)(h1p + 128);
                int o = rr * 2;
                float W0[4] = {c[0][o], c[0][o + 1], c[1][o], c[1][o + 1]};
                float W1[4] = {c[2][o], c[2][o + 1], c[3][o], c[3][o + 1]};
                float W2[4] = {c[4][o], c[4][o + 1], c[5][o], c[5][o + 1]};
                float W3[4] = {c[6][o], c[6][o + 1], c[7][o], c[7][o + 1]};
                const float* S0 = (const float*)&s0;
                const float* SX = (const float*)&sx;
                const float* SYv = (const float*)&sy;
                const float* SZ = (const float*)&sz;
                float A0[4], B0[4], AX[4], AY[4], AZ[4], BX[4], BY[4], BZ[4];
                #pragma unroll
                for (int i = 0; i < 4; i++) {
                    float dd = SX[i] * y1x + SYv[i] * y1y + SZ[i] * y1z;
                    A0[i] = cN * W0[i] * S0[i] * y0;
                    B0[i] = cN * W1[i] * dd * SQRT3_INV;
                    float t2 = cN * W2[i] * S0[i];
                    AX[i] = t2 * y1x; AY[i] = t2 * y1y; AZ[i] = t2 * y1z;
                    float t3 = cN * W3[i] * y0;
                    BX[i] = t3 * SX[i]; BY[i] = t3 * SYv[i]; BZ[i] = t3 * SZ[i];
                }
                float* a0b = g_a0 + (size_t)rc * 128 + m0;
                float* a1b = g_a1 + (size_t)rc * 384 + m0;
                red4(a0b,       A0[0], A0[1], A0[2], A0[3]);
                red4(a0b + 64,  B0[0], B0[1], B0[2], B0[3]);
                red4(a1b,       AX[0], AX[1], AX[2], AX[3]);
                red4(a1b + 64,  BX[0], BX[1], BX[2], BX[3]);
                red4(a1b + 128, AY[0], AY[1], AY[2], AY[3]);
                red4(a1b + 192, BY[0], BY[1], BY[2], BY[3]);
                red4(a1b + 256, AZ[0], AZ[1], AZ[2], AZ[3]);
                red4(a1b + 320, BZ[0], BZ[1], BZ[2], BZ[3]);
            }
        }
        __syncthreads();
    }
}

// ---------------- K4a: linear_down (role-split, 2 CTA/SM) -------------------
// role 0: d0 (Wd0 64KB + A0 16KB); role 1: d1 (Wd1 32KB + A1 48KB)
#define K4A_SMEM_BYTES (20480 * 4)

__global__ void __launch_bounds__(256, 2)
k_lin_down(const float* __restrict__ Wd0, const float* __restrict__ Wd1) {
    extern __shared__ float sm[];
    int t = threadIdx.x;
    int w = t >> 5, l = t & 31;
    int role = blockIdx.x & 1;
    const int step = gridDim.x >> 1;
    const float inv2 = 0.08838834764831845f;  // 1/sqrt(128)

    if (role == 0) {
        float* sWd0 = sm;
        float* sA0  = sm + 16384;
        for (int i = t; i < 4096; i += 256) ((float4*)sWd0)[i] = ((const float4*)Wd0)[i];
        for (int tile = blockIdx.x >> 1; tile < NN / 32; tile += step) {
            int nb = tile * 32;
            for (int i = t; i < 1024; i += 256)
                ((float4*)sA0)[i] = ((const float4*)(g_a0 + (size_t)nb * 128))[i];
            __syncthreads();
            int k4 = l * 4;
            float acc[4][4];
            #pragma unroll
            for (int j = 0; j < 4; j++) { acc[j][0] = acc[j][1] = acc[j][2] = acc[j][3] = 0.f; }
            #pragma unroll 4
            for (int m = 0; m < 128; m++) {
                float4 wv = *(const float4*)&sWd0[m * 128 + k4];
                #pragma unroll
                for (int j = 0; j < 4; j++) {
                    float a = sA0[(w * 4 + j) * 128 + m];
                    acc[j][0] += a * wv.x; acc[j][1] += a * wv.y;
                    acc[j][2] += a * wv.z; acc[j][3] += a * wv.w;
                }
            }
            #pragma unroll
            for (int j = 0; j < 4; j++) {
                float4 o = make_float4(acc[j][0] * inv2, acc[j][1] * inv2,
                                       acc[j][2] * inv2, acc[j][3] * inv2);
                *(float4*)&g_d0[(size_t)(nb + w * 4 + j) * 128 + k4] = o;
            }
            __syncthreads();
        }
    } else {
        float* sWd1 = sm;
        float* sA1  = sm + 8192;
        for (int i = t; i < 2048; i += 256) ((float4*)sWd1)[i] = ((const float4*)Wd1)[i];
        for (int tile = blockIdx.x >> 1; tile < NN / 32; tile += step) {
            int nb = tile * 32;
            for (int i = t; i < 3072; i += 256)
                ((float4*)sA1)[i] = ((const float4*)(g_a1 + (size_t)nb * 384))[i];
            __syncthreads();
            #pragma unroll
            for (int rep = 0; rep < 3; rep++) {
                int u = w + rep * 8;
                int c = u % 3, gg = u / 3;
                int k2 = l * 2;
                float acc[4][2];
                #pragma unroll
                for (int j = 0; j < 4; j++) { acc[j][0] = acc[j][1] = 0.f; }
                #pragma unroll 4
                for (int m = 0; m < 128; m++) {
                    float2 wv = *(const float2*)&sWd1[m * 64 + k2];
                    #pragma unroll
                    for (int j = 0; j < 4; j++) {
                        float a = sA1[(gg * 4 + j) * 384 + c * 128 + m];
                        acc[j][0] += a * wv.x; acc[j][1] += a * wv.y;
                    }
                }
                #pragma unroll
                for (int j = 0; j < 4; j++) {
                    float2 o = make_float2(acc[j][0] * inv2, acc[j][1] * inv2);
                    *(float2*)&g_d1[(size_t)(nb + gg * 4 + j) * 192 + c * 64 + k2] = o;
                }
            }
            __syncthreads();
        }
    }
}

// ---------------- K4b: species self-connection + gate + output --------------
#define K4B_SMEM_BYTES (50176 * 4)

__global__ void k_self_gate(const float* __restrict__ x0, const float* __restrict__ x1,
                            const int* __restrict__ species,
                            const float* __restrict__ Wsc0, const float* __restrict__ Wsc1,
                            float* __restrict__ out) {
    extern __shared__ float sm[];
    float* sW0 = sm;
    float* sW1 = sm + 32768;
    float* sX0 = sm + 49152;
    float* sX1 = sm + 49408;
    int t = threadIdx.x;
    for (int i = t; i < 32768; i += 256) sW0[i] = Wsc0[i];
    for (int i = t; i < 16384; i += 256) sW1[i] = Wsc1[i];
    float* outv = out + (size_t)NN * 64;
    int ng = NN / 4;
    for (int gId = blockIdx.x; gId < ng; gId += gridDim.x) {
        int nb = gId * 4;
        sX0[t] = x0[nb * 64 + t];
        for (int i = t; i < 768; i += 256) sX1[i] = x1[nb * 192 + i];
        __syncthreads();
        int ln = t >> 6, k = t & 63;
        int n = nb + ln;
        int sp = species[n];
        const float* w0 = sW0 + sp * 8192;
        const float* w1 = sW1 + sp * 4096;
        float aA = 0.f, aB = 0.f, c0 = 0.f, c1 = 0.f, c2 = 0.f;
        #pragma unroll 8
        for (int m = 0; m < 64; m++) {
            float xv = sX0[ln * 64 + m];
            aA += xv * w0[m * 128 + k];
            aB += xv * w0[m * 128 + 64 + k];
            float vx = sX1[ln * 192 + m * 3 + 0];
            float vy = sX1[ln * 192 + m * 3 + 1];
            float vz = sX1[ln * 192 + m * 3 + 2];
            float wm = w1[m * 64 + k];
            c0 += vx * wm; c1 += vy * wm; c2 += vz * wm;
        }
        const float inv = 0.125f;
        float f0a = 0.5f * (g_d0[n * 128 + k]      + aA * inv);
        float f0b = 0.5f * (g_d0[n * 128 + 64 + k] + aB * inv);
        float scal = silu_f(f0a);
        float gate = silu_f(f0b);
        out[(size_t)n * 64 + k] = scal;
        float v0 = 0.5f * (g_d1[n * 192 + 0   + k] + c0 * inv) * gate;
        float v1 = 0.5f * (g_d1[n * 192 + 64  + k] + c1 * inv) * gate;
        float v2 = 0.5f * (g_d1[n * 192 + 128 + k] + c2 * inv) * gate;
        outv[(size_t)n * 192 + k * 3 + 0] = v0;
        outv[(size_t)n * 192 + k * 3 + 1] = v1;
        outv[(size_t)n * 192 + k * 3 + 2] = v2;
        __syncthreads();
    }
}

// ---------------- launch -----------------------------------------------------
extern "C" void kernel_launch(void* const* d_in, const int* in_sizes, int n_in,
                              void* d_out, int out_size) {
    const float* x0   = (const float*)d_in[0];
    const float* x1   = (const float*)d_in[1];
    const float* ey0  = (const float*)d_in[2];
    const float* ey1  = (const float*)d_in[3];
    const float* re   = (const float*)d_in[4];
    const int*   snd  = (const int*)d_in[5];
    const int*   rcv  = (const int*)d_in[6];
    const int*   spc  = (const int*)d_in[7];
    const float* Wup0 = (const float*)d_in[8];
    const float* Wup1 = (const float*)d_in[9];
    const float* Rw1  = (const float*)d_in[10];
    const float* Rw2  = (const float*)d_in[11];
    const float* Wd0  = (const float*)d_in[12];
    const float* Wd1  = (const float*)d_in[13];
    const float* Wsc0 = (const float*)d_in[14];
    const float* Wsc1 = (const float*)d_in[15];
    float* out = (float*)d_out;

    cudaFuncSetAttribute(k_edge,      cudaFuncAttributeMaxDynamicSharedMemorySize, K3_SMEM_BYTES);
    cudaFuncSetAttribute(k_lin_down,  cudaFuncAttributeMaxDynamicSharedMemorySize, K4A_SMEM_BYTES);
    cudaFuncSetAttribute(k_self_gate, cudaFuncAttributeMaxDynamicSharedMemorySize, K4B_SMEM_BYTES);

    k_zero<<<2048, 256>>>();
    k_linear_up<<<NN / 16, 256>>>(x0, x1, Wup0, Wup1);
    k_edge<<<296, 256, K3_SMEM_BYTES>>>(re, ey0, ey1, snd, rcv, Rw1, Rw2);
    k_lin_down<<<296, 256, K4A_SMEM_BYTES>>>(Wd0, Wd1);
    k_self_gate<<<148, 256, K4B_SMEM_BYTES>>>(x0, x1, spc, Wsc0, Wsc1, out);
}